// round 15
// baseline (speedup 1.0000x reference)
#include <cuda_runtime.h>

// Problem dims
#define T_DIM 4
#define B_DIM 32
#define C_DIM 512
#define N_DIM 196
#define H_DIM 2048
#define J_DIM (B_DIM * N_DIM)          // 6272 = 49 * 128
#define JW    (J_DIM / 32)             // 196 mask words per (t,h)
#define HJ (H_DIM * J_DIM)             // 12,845,056
#define CJ (C_DIM * J_DIM)             //  3,211,264

// Scratch (static device memory)
__device__ float    g_xT[T_DIM * CJ];       // x transposed: (t, c, j)
__device__ float    g_w1T[C_DIM * H_DIM];   // w1 transposed to [C, H] (k-major)
__device__ float    g_h[T_DIM * HJ];        // hidden pre-act
__device__ float    g_o[T_DIM * CJ];        // output pre-act
__device__ float    g_w2T[H_DIM * C_DIM];   // w2 transposed to [H, C]
__device__ unsigned g_mask[T_DIM * JW * H_DIM]; // spike bits, layout [t][jw][h]
__device__ float    g_mean1[H_DIM];
__device__ float    g_rstd1[H_DIM];
__device__ float    g_mean2[C_DIM];
__device__ float    g_rstd2[C_DIM];

// ---- packed fp32x2 helpers --------------------------------------------------
__device__ __forceinline__ unsigned long long bcast2(float s) {
    unsigned long long d;
    asm("mov.b64 %0, {%1, %1};" : "=l"(d) : "f"(s));
    return d;
}
__device__ __forceinline__ void fma2(unsigned long long& acc,
                                     unsigned long long a,
                                     unsigned long long b) {
    asm("fma.rn.f32x2 %0, %1, %2, %0;" : "+l"(acc) : "l"(a), "l"(b));
}
__device__ __forceinline__ void unpack2(unsigned long long v, float& lo, float& hi) {
    asm("mov.b64 {%0, %1}, %2;" : "=f"(lo), "=f"(hi) : "l"(v));
}
__device__ __forceinline__ void cp16(void* smem_dst, const void* gmem_src) {
    unsigned s = (unsigned)__cvta_generic_to_shared(smem_dst);
    asm volatile("cp.async.cg.shared.global [%0], [%1], 16;" :: "r"(s), "l"(gmem_src));
}

// ---------------------------------------------------------------------------
// K0: transpose x (t,b,c,n) -> g_xT (t,c,j=b*n), float4 both sides.
// ---------------------------------------------------------------------------
__global__ void transpose_x(const float* __restrict__ x) {
    int idx = blockIdx.x * blockDim.x + threadIdx.x;   // over T*CJ/4
    int base = idx << 2;
    int t   = base / CJ;
    int rem = base - t * CJ;
    int c   = rem / J_DIM;
    int j   = rem - c * J_DIM;
    int b   = j / N_DIM;
    int n   = j - b * N_DIM;                            // n%4==0, n+3<196
    float4 v = *(const float4*)&x[((t * B_DIM + b) * C_DIM + c) * N_DIM + n];
    *(float4*)&g_xT[base] = v;
}

// ---------------------------------------------------------------------------
// K0a: transpose w1 [H,C] -> g_w1T [C,H]  (k-major A for cp.async)
// ---------------------------------------------------------------------------
__global__ void transpose_w1(const float* __restrict__ w1) {
    __shared__ float tile[32][33];
    int h0 = blockIdx.x * 32, c0 = blockIdx.y * 32;
    for (int r = threadIdx.y; r < 32; r += 8)
        tile[r][threadIdx.x] = w1[(h0 + r) * C_DIM + c0 + threadIdx.x];
    __syncthreads();
    for (int r = threadIdx.y; r < 32; r += 8)
        g_w1T[(c0 + r) * H_DIM + h0 + threadIdx.x] = tile[threadIdx.x][r];
}

// ---------------------------------------------------------------------------
// K0b: transpose w2 [C,H] -> g_w2T [H,C]
// ---------------------------------------------------------------------------
__global__ void transpose_w2(const float* __restrict__ w2) {
    __shared__ float tile[32][33];
    int h0 = blockIdx.x * 32, c0 = blockIdx.y * 32;
    for (int r = threadIdx.y; r < 32; r += 8)
        tile[r][threadIdx.x] = w2[(c0 + r) * H_DIM + h0 + threadIdx.x];
    __syncthreads();
    for (int r = threadIdx.y; r < 32; r += 8)
        g_w2T[(h0 + r) * C_DIM + c0 + threadIdx.x] = tile[threadIdx.x][r];
}

// ---------------------------------------------------------------------------
// K1: PERSISTENT SGEMM h = w1T^T @ xT per t. FFMA2 inner, 2-stage cp.async.
// 296 CTAs (2/SM x 148 SMs) loop over the 3136 tiles -> no wave-tail
// quantization. Per-tile body is byte-identical to the converged R9 kernel
// (bit-identical arithmetic). Tile order: mb fastest (B-tile reuse in L2).
// ---------------------------------------------------------------------------
#define BK1     16
#define NTILES  (16 * 49 * T_DIM)      // 3136
#define SG_GRID 296
__global__ __launch_bounds__(256, 2) void sgemm1(
    const float* __restrict__ A, const float* __restrict__ B,
    float* __restrict__ C) {
    __shared__ float As[2][BK1][128];
    __shared__ float Bs[2][BK1][128];

    int tid = threadIdx.x;
    int tx = tid & 15;
    int ty = tid >> 4;
    int lk = tid >> 5;
    int lc = (tid & 31) << 2;

    for (int tile = blockIdx.x; tile < NTILES; tile += SG_GRID) {
        int mb   = tile & 15;
        int rest = tile >> 4;            // 0..195
        int nb   = rest % 49;
        int t    = rest / 49;
        int m0 = mb << 7;
        int n0 = nb << 7;
        const float* Bt = B + t * CJ;
        float*       Ct = C + t * HJ;

        const float* Agp = A  + lk * H_DIM + m0 + lc;
        const float* Bgp = Bt + lk * J_DIM + n0 + lc;

        unsigned long long acc[4][8];
#pragma unroll
        for (int p = 0; p < 4; p++)
#pragma unroll
            for (int j = 0; j < 8; j++) acc[p][j] = 0ull;

        cp16(&As[0][lk][lc],     Agp);
        cp16(&As[0][lk + 8][lc], Agp + 8 * H_DIM);
        cp16(&Bs[0][lk][lc],     Bgp);
        cp16(&Bs[0][lk + 8][lc], Bgp + 8 * J_DIM);
        asm volatile("cp.async.commit_group;");
        asm volatile("cp.async.wait_group 0;");
        __syncthreads();

        int buf = 0;
        for (int s = 1; s <= 512 / BK1; s++) {
            if (s < 512 / BK1) {
                const float* Ag = Agp + s * BK1 * H_DIM;
                const float* Bg = Bgp + s * BK1 * J_DIM;
                cp16(&As[buf ^ 1][lk][lc],     Ag);
                cp16(&As[buf ^ 1][lk + 8][lc], Ag + 8 * H_DIM);
                cp16(&Bs[buf ^ 1][lk][lc],     Bg);
                cp16(&Bs[buf ^ 1][lk + 8][lc], Bg + 8 * J_DIM);
                asm volatile("cp.async.commit_group;");
            }
#pragma unroll
            for (int k = 0; k < BK1; k++) {
                ulonglong2 A0 = *(const ulonglong2*)&As[buf][k][ty << 2];
                ulonglong2 A1 = *(const ulonglong2*)&As[buf][k][(ty << 2) + 64];
                float4 rb0 = *(const float4*)&Bs[buf][k][tx << 2];
                float4 rb1 = *(const float4*)&Bs[buf][k][(tx << 2) + 64];
                unsigned long long ap[4] = {A0.x, A0.y, A1.x, A1.y};
                float rb[8] = {rb0.x, rb0.y, rb0.z, rb0.w, rb1.x, rb1.y, rb1.z, rb1.w};
#pragma unroll
                for (int j = 0; j < 8; j++) {
                    unsigned long long bb = bcast2(rb[j]);
#pragma unroll
                    for (int p = 0; p < 4; p++)
                        fma2(acc[p][j], ap[p], bb);
                }
            }
            if (s < 512 / BK1) {
                asm volatile("cp.async.wait_group 0;");
                __syncthreads();
                buf ^= 1;
            }
        }

#pragma unroll
        for (int p = 0; p < 4; p++) {
            int mLo = m0 + (ty << 2) + ((p < 2) ? (p << 1) : (64 + ((p - 2) << 1)));
            float lo[8], hi[8];
#pragma unroll
            for (int j = 0; j < 8; j++) unpack2(acc[p][j], lo[j], hi[j]);
            float* r0 = Ct + mLo * J_DIM + n0 + (tx << 2);
            float* r1 = r0 + J_DIM;
            *(float4*)r0        = make_float4(lo[0], lo[1], lo[2], lo[3]);
            *(float4*)(r0 + 64) = make_float4(lo[4], lo[5], lo[6], lo[7]);
            *(float4*)r1        = make_float4(hi[0], hi[1], hi[2], hi[3]);
            *(float4*)(r1 + 64) = make_float4(hi[4], hi[5], hi[6], hi[7]);
        }
        // Next tile's prologue writes smem buffer 0 while the last compute
        // read buffer 1; the prologue's wait+__syncthreads re-synchronizes.
    }
}

// ---------------------------------------------------------------------------
// BN stats: one CTA per channel, fp64 accumulate, 2 float4 streams (MLP=2).
// ---------------------------------------------------------------------------
__global__ __launch_bounds__(256) void bn_stats(
    const float* __restrict__ X, int tStride,
    float* __restrict__ meanOut, float* __restrict__ rstdOut) {
    int ch = blockIdx.x;
    const float* base = X + ch * J_DIM;
    double s1a = 0.0, s2a = 0.0, s1b = 0.0, s2b = 0.0;
    for (int t = 0; t < T_DIM; t++) {
        const float* p = base + t * tStride;
        for (int j = threadIdx.x * 8; j + 7 < J_DIM; j += 2048) {
            float4 va = *(const float4*)&p[j];
            float4 vb = *(const float4*)&p[j + 4];
            double a0 = va.x, a1 = va.y, a2 = va.z, a3 = va.w;
            double b0 = vb.x, b1 = vb.y, b2 = vb.z, b3 = vb.w;
            s1a += a0 + a1 + a2 + a3;
            s2a += a0 * a0 + a1 * a1 + a2 * a2 + a3 * a3;
            s1b += b0 + b1 + b2 + b3;
            s2b += b0 * b0 + b1 * b1 + b2 * b2 + b3 * b3;
        }
    }
    __shared__ double sh1[256];
    __shared__ double sh2[256];
    sh1[threadIdx.x] = s1a + s1b;
    sh2[threadIdx.x] = s2a + s2b;
    __syncthreads();
    for (int s = 128; s > 0; s >>= 1) {
        if (threadIdx.x < s) {
            sh1[threadIdx.x] += sh1[threadIdx.x + s];
            sh2[threadIdx.x] += sh2[threadIdx.x + s];
        }
        __syncthreads();
    }
    if (threadIdx.x == 0) {
        double n    = (double)T_DIM * (double)J_DIM;
        double mean = sh1[0] / n;
        double var  = sh2[0] / n - mean * mean;
        meanOut[ch] = (float)mean;
        rstdOut[ch] = __frsqrt_rn(__fadd_rn((float)var, 1e-5f));
    }
}

// ---------------------------------------------------------------------------
// BN1 + LIF1 -> spike bitmask only.
// ---------------------------------------------------------------------------
__global__ __launch_bounds__(256) void lif1_mask(
    const float* __restrict__ gamma, const float* __restrict__ beta) {
    int gw   = (blockIdx.x << 3) + (threadIdx.x >> 5);  // global warp id
    int lane = threadIdx.x & 31;
    int h  = gw & (H_DIM - 1);
    int jw = gw >> 11;                                   // 0..195
    float m = g_mean1[h], r = g_rstd1[h];
    float g = gamma[h],   bt = beta[h];
    const float* p = g_h + h * J_DIM + (jw << 5) + lane;
    float v = 0.0f;
#pragma unroll
    for (int t = 0; t < T_DIM; t++) {
        float x = p[t * HJ];
        x = __fadd_rn(__fmul_rn(__fmul_rn(__fsub_rn(x, m), r), g), bt);
        v = __fadd_rn(v, __fmul_rn(__fsub_rn(x, v), 0.5f));
        unsigned mw = __ballot_sync(0xffffffffu, v >= 1.0f);
        if (lane == 0) g_mask[(t * JW + jw) * H_DIM + h] = mw;
        v = (v >= 1.0f) ? 0.0f : v;
    }
}

// ---------------------------------------------------------------------------
// K4: sparse spike GEMM, 2 columns per warp (R11/R13 scalar version —
// best measured; converged, do not touch).
// ---------------------------------------------------------------------------
__global__ __launch_bounds__(1024) void spmm2() {
    __shared__ __align__(16) unsigned char shraw[128 * 65 * 4];  // 33.3 KB
    unsigned* words0 = (unsigned*)shraw;                // [2048] masks for jw0
    unsigned* words1 = (unsigned*)shraw + H_DIM;        // [2048] masks for jw0+1
    float*    buf    = (float*)shraw;                   // epilogue: 128 x 65

    int tid  = threadIdx.x;
    int w    = tid >> 5;                     // warp id = local column (0..31)
    int lane = tid & 31;
    int j0   = blockIdx.x * 64;
    int jw0  = blockIdx.x * 2;
    int t    = blockIdx.y;

    // Phase 1: contiguous mask loads for both jw blocks.
    {
        const unsigned* mp0 = g_mask + (t * JW + jw0)     * H_DIM;
        const unsigned* mp1 = g_mask + (t * JW + jw0 + 1) * H_DIM;
        words0[tid]        = mp0[tid];
        words0[tid + 1024] = mp0[tid + 1024];
        words1[tid]        = mp1[tid];
        words1[tid + 1024] = mp1[tid + 1024];
    }
    __syncthreads();

    // Phase 2: gather active rows for columns A = j0+w, B = j0+32+w.
    float4 aA0 = make_float4(0.f, 0.f, 0.f, 0.f);
    float4 aA1 = aA0, aA2 = aA0, aA3 = aA0;
    float4 aB0 = aA0, aB1 = aA0, aB2 = aA0, aB3 = aA0;
    int c0 = lane << 2;
    for (int wi = 0; wi < H_DIM / 32; wi++) {
        unsigned bA = (words0[(wi << 5) + lane] >> w) & 1u;
        unsigned bB = (words1[(wi << 5) + lane] >> w) & 1u;
        unsigned mA = __ballot_sync(0xffffffffu, bA);
        unsigned mB = __ballot_sync(0xffffffffu, bB);
        unsigned mU = mA | mB;
        while (mU) {
            int b = __ffs(mU) - 1;
            mU &= mU - 1;
            int h = (wi << 5) + b;
            const float* rp = g_w2T + h * C_DIM + c0;
            float4 v0 = *(const float4*)(rp);
            float4 v1 = *(const float4*)(rp + 128);
            float4 v2 = *(const float4*)(rp + 256);
            float4 v3 = *(const float4*)(rp + 384);
            if ((mA >> b) & 1u) {
                aA0.x += v0.x; aA0.y += v0.y; aA0.z += v0.z; aA0.w += v0.w;
                aA1.x += v1.x; aA1.y += v1.y; aA1.z += v1.z; aA1.w += v1.w;
                aA2.x += v2.x; aA2.y += v2.y; aA2.z += v2.z; aA2.w += v2.w;
                aA3.x += v3.x; aA3.y += v3.y; aA3.z += v3.z; aA3.w += v3.w;
            }
            if ((mB >> b) & 1u) {
                aB0.x += v0.x; aB0.y += v0.y; aB0.z += v0.z; aB0.w += v0.w;
                aB1.x += v1.x; aB1.y += v1.y; aB1.z += v1.z; aB1.w += v1.w;
                aB2.x += v2.x; aB2.y += v2.y; aB2.z += v2.z; aB2.w += v2.w;
                aB3.x += v3.x; aB3.y += v3.y; aB3.z += v3.z; aB3.w += v3.w;
            }
        }
    }

    // Epilogue: per q, stage 128 c-rows x 64 cols (stride 65), write coalesced.
#pragma unroll
    for (int q = 0; q < 4; q++) {
        float4 vA = (q == 0) ? aA0 : (q == 1) ? aA1 : (q == 2) ? aA2 : aA3;
        float4 vB = (q == 0) ? aB0 : (q == 1) ? aB1 : (q == 2) ? aB2 : aB3;
        __syncthreads();                     // protects mask region reuse / buf reuse
        float fa[4] = {vA.x, vA.y, vA.z, vA.w};
        float fb[4] = {vB.x, vB.y, vB.z, vB.w};
#pragma unroll
        for (int i = 0; i < 4; i++) {
            buf[(c0 + i) * 65 + w]      = fa[i];
            buf[(c0 + i) * 65 + 32 + w] = fb[i];
        }
        __syncthreads();
#pragma unroll
        for (int e0 = 0; e0 < 2; e0++) {
            int e  = tid + e0 * 1024;        // 2048 float4 = 128 rows x 16
            int cl = e >> 4;
            int jj = (e & 15) << 2;
            float4 o;
            o.x = buf[cl * 65 + jj + 0];
            o.y = buf[cl * 65 + jj + 1];
            o.z = buf[cl * 65 + jj + 2];
            o.w = buf[cl * 65 + jj + 3];
            *(float4*)&g_o[t * CJ + (q * 128 + cl) * J_DIM + j0 + jj] = o;
        }
    }
}

// ---------------------------------------------------------------------------
// BN2 + LIF2 + transpose to (T,B,C,N), float4.
// ---------------------------------------------------------------------------
__global__ __launch_bounds__(256) void bn_lif2(
    const float* __restrict__ gamma, const float* __restrict__ beta,
    float* __restrict__ out) {
    int idx = blockIdx.x * blockDim.x + threadIdx.x;   // over CJ/4
    int base = idx << 2;
    int c = base / J_DIM;
    int j = base - c * J_DIM;
    int b = j / N_DIM;
    int n = j - b * N_DIM;
    float m = g_mean2[c], r = g_rstd2[c];
    float g = gamma[c],   bt = beta[c];
    float v0 = 0.f, v1 = 0.f, v2 = 0.f, v3 = 0.f;
#pragma unroll
    for (int t = 0; t < T_DIM; t++) {
        float4 x = *(const float4*)&g_o[base + t * CJ];
        float a0 = __fadd_rn(__fmul_rn(__fmul_rn(__fsub_rn(x.x, m), r), g), bt);
        float a1 = __fadd_rn(__fmul_rn(__fmul_rn(__fsub_rn(x.y, m), r), g), bt);
        float a2 = __fadd_rn(__fmul_rn(__fmul_rn(__fsub_rn(x.z, m), r), g), bt);
        float a3 = __fadd_rn(__fmul_rn(__fmul_rn(__fsub_rn(x.w, m), r), g), bt);
        v0 = __fadd_rn(v0, __fmul_rn(__fsub_rn(a0, v0), 0.5f));
        v1 = __fadd_rn(v1, __fmul_rn(__fsub_rn(a1, v1), 0.5f));
        v2 = __fadd_rn(v2, __fmul_rn(__fsub_rn(a2, v2), 0.5f));
        v3 = __fadd_rn(v3, __fmul_rn(__fsub_rn(a3, v3), 0.5f));
        float4 s;
        s.x = (v0 >= 1.0f) ? 1.0f : 0.0f;
        s.y = (v1 >= 1.0f) ? 1.0f : 0.0f;
        s.z = (v2 >= 1.0f) ? 1.0f : 0.0f;
        s.w = (v3 >= 1.0f) ? 1.0f : 0.0f;
        *(float4*)&out[((t * B_DIM + b) * C_DIM + c) * N_DIM + n] = s;
        v0 = (v0 >= 1.0f) ? 0.0f : v0;
        v1 = (v1 >= 1.0f) ? 0.0f : v1;
        v2 = (v2 >= 1.0f) ? 0.0f : v2;
        v3 = (v3 >= 1.0f) ? 0.0f : v3;
    }
}

// ---------------------------------------------------------------------------
// kernel_launch. Inputs: 0:x 1:w1 2:g1 3:b1 4:w2 5:g2 6:b2
// sgemm1 is launch #4 -> profiled by ncu.
// ---------------------------------------------------------------------------
extern "C" void kernel_launch(void* const* d_in, const int* in_sizes, int n_in,
                              void* d_out, int out_size) {
    const float* x  = (const float*)d_in[0];
    const float* w1 = (const float*)d_in[1];
    const float* g1 = (const float*)d_in[2];
    const float* b1 = (const float*)d_in[3];
    const float* w2 = (const float*)d_in[4];
    const float* g2 = (const float*)d_in[5];
    const float* b2 = (const float*)d_in[6];
    float* out = (float*)d_out;

    float *p_xT, *p_w1T, *p_h, *p_o, *p_m1, *p_r1, *p_m2, *p_r2;
    cudaGetSymbolAddress((void**)&p_xT,  g_xT);
    cudaGetSymbolAddress((void**)&p_w1T, g_w1T);
    cudaGetSymbolAddress((void**)&p_h,   g_h);
    cudaGetSymbolAddress((void**)&p_o,   g_o);
    cudaGetSymbolAddress((void**)&p_m1,  g_mean1);
    cudaGetSymbolAddress((void**)&p_r1,  g_rstd1);
    cudaGetSymbolAddress((void**)&p_m2,  g_mean2);
    cudaGetSymbolAddress((void**)&p_r2,  g_rstd2);

    transpose_x<<<(T_DIM * CJ / 4) / 256, 256>>>(x);                        // 1
    transpose_w1<<<dim3(H_DIM / 32, C_DIM / 32), dim3(32, 8)>>>(w1);        // 2
    transpose_w2<<<dim3(H_DIM / 32, C_DIM / 32), dim3(32, 8)>>>(w2);        // 3
    sgemm1<<<SG_GRID, 256>>>(p_w1T, p_xT, p_h);                             // 4 <- profiled
    bn_stats<<<H_DIM, 256>>>(p_h, HJ, p_m1, p_r1);                          // 5
    lif1_mask<<<(H_DIM * JW) / 8, 256>>>(g1, b1);                           // 6
    spmm2<<<dim3(J_DIM / 64, T_DIM), 1024>>>();                             // 7
    bn_stats<<<C_DIM, 256>>>(p_o, CJ, p_m2, p_r2);                          // 8
    bn_lif2<<<(CJ / 4) / 256, 256>>>(g2, b2, out);                          // 9
}

// round 16
// speedup vs baseline: 1.0241x; 1.0241x over previous
#include <cuda_runtime.h>

// Problem dims
#define T_DIM 4
#define B_DIM 32
#define C_DIM 512
#define N_DIM 196
#define H_DIM 2048
#define J_DIM (B_DIM * N_DIM)          // 6272 = 49 * 128
#define JW    (J_DIM / 32)             // 196 mask words per (t,h)
#define HJ (H_DIM * J_DIM)             // 12,845,056
#define CJ (C_DIM * J_DIM)             //  3,211,264

// Scratch (static device memory)
__device__ float    g_xT[T_DIM * CJ];       // x transposed: (t, c, j)
__device__ float    g_w1T[C_DIM * H_DIM];   // w1 transposed to [C, H] (k-major)
__device__ float    g_h[T_DIM * HJ];        // hidden pre-act
__device__ float    g_o[T_DIM * CJ];        // output pre-act
__device__ float    g_w2T[H_DIM * C_DIM];   // w2 transposed to [H, C]
__device__ unsigned g_mask[T_DIM * JW * H_DIM]; // spike bits, layout [t][jw][h]
__device__ float    g_mean1[H_DIM];
__device__ float    g_rstd1[H_DIM];
__device__ float    g_mean2[C_DIM];
__device__ float    g_rstd2[C_DIM];

// ---- packed fp32x2 helpers --------------------------------------------------
__device__ __forceinline__ unsigned long long bcast2(float s) {
    unsigned long long d;
    asm("mov.b64 %0, {%1, %1};" : "=l"(d) : "f"(s));
    return d;
}
__device__ __forceinline__ void fma2(unsigned long long& acc,
                                     unsigned long long a,
                                     unsigned long long b) {
    asm("fma.rn.f32x2 %0, %1, %2, %0;" : "+l"(acc) : "l"(a), "l"(b));
}
__device__ __forceinline__ void unpack2(unsigned long long v, float& lo, float& hi) {
    asm("mov.b64 {%0, %1}, %2;" : "=f"(lo), "=f"(hi) : "l"(v));
}
__device__ __forceinline__ void cp16(void* smem_dst, const void* gmem_src) {
    unsigned s = (unsigned)__cvta_generic_to_shared(smem_dst);
    asm volatile("cp.async.cg.shared.global [%0], [%1], 16;" :: "r"(s), "l"(gmem_src));
}

// ---------------------------------------------------------------------------
// K0: transpose x (t,b,c,n) -> g_xT (t,c,j=b*n), float4 both sides.
// ---------------------------------------------------------------------------
__global__ void transpose_x(const float* __restrict__ x) {
    int idx = blockIdx.x * blockDim.x + threadIdx.x;   // over T*CJ/4
    int base = idx << 2;
    int t   = base / CJ;
    int rem = base - t * CJ;
    int c   = rem / J_DIM;
    int j   = rem - c * J_DIM;
    int b   = j / N_DIM;
    int n   = j - b * N_DIM;                            // n%4==0, n+3<196
    float4 v = *(const float4*)&x[((t * B_DIM + b) * C_DIM + c) * N_DIM + n];
    *(float4*)&g_xT[base] = v;
}

// ---------------------------------------------------------------------------
// K0ab: transpose both weights in one launch.
// z=0: w1 [H,C] -> g_w1T [C,H].  z=1: w2 [C,H] -> g_w2T [H,C].
// ---------------------------------------------------------------------------
__global__ void transpose_w(const float* __restrict__ w1,
                            const float* __restrict__ w2) {
    __shared__ float tile[32][33];
    int h0 = blockIdx.x * 32, c0 = blockIdx.y * 32;
    if (blockIdx.z == 0) {
        for (int r = threadIdx.y; r < 32; r += 8)
            tile[r][threadIdx.x] = w1[(h0 + r) * C_DIM + c0 + threadIdx.x];
        __syncthreads();
        for (int r = threadIdx.y; r < 32; r += 8)
            g_w1T[(c0 + r) * H_DIM + h0 + threadIdx.x] = tile[threadIdx.x][r];
    } else {
        for (int r = threadIdx.y; r < 32; r += 8)
            tile[r][threadIdx.x] = w2[(c0 + r) * H_DIM + h0 + threadIdx.x];
        __syncthreads();
        for (int r = threadIdx.y; r < 32; r += 8)
            g_w2T[(h0 + r) * C_DIM + c0 + threadIdx.x] = tile[threadIdx.x][r];
    }
}

// ---------------------------------------------------------------------------
// K1: SGEMM h = w1T^T @ xT per t. FFMA2 inner, 2-stage cp.async pipeline.
// (R9/R13 version — best measured; converged.)
// ---------------------------------------------------------------------------
#define BK1 16
__global__ __launch_bounds__(256, 2) void sgemm1(
    const float* __restrict__ A, const float* __restrict__ B,
    float* __restrict__ C) {
    __shared__ float As[2][BK1][128];
    __shared__ float Bs[2][BK1][128];

    const float* Bt = B + blockIdx.z * CJ;
    float*       Ct = C + blockIdx.z * HJ;

    int tid = threadIdx.x;
    int m0 = blockIdx.x * 128;
    int n0 = blockIdx.y * 128;

    int tx = tid & 15;
    int ty = tid >> 4;

    int lk = tid >> 5;
    int lc = (tid & 31) << 2;
    const float* Agp = A  + lk * H_DIM + m0 + lc;
    const float* Bgp = Bt + lk * J_DIM + n0 + lc;

    unsigned long long acc[4][8];
#pragma unroll
    for (int p = 0; p < 4; p++)
#pragma unroll
        for (int j = 0; j < 8; j++) acc[p][j] = 0ull;

    cp16(&As[0][lk][lc],     Agp);
    cp16(&As[0][lk + 8][lc], Agp + 8 * H_DIM);
    cp16(&Bs[0][lk][lc],     Bgp);
    cp16(&Bs[0][lk + 8][lc], Bgp + 8 * J_DIM);
    asm volatile("cp.async.commit_group;");
    asm volatile("cp.async.wait_group 0;");
    __syncthreads();

    int buf = 0;
    for (int s = 1; s <= 512 / BK1; s++) {
        if (s < 512 / BK1) {
            const float* Ag = Agp + s * BK1 * H_DIM;
            const float* Bg = Bgp + s * BK1 * J_DIM;
            cp16(&As[buf ^ 1][lk][lc],     Ag);
            cp16(&As[buf ^ 1][lk + 8][lc], Ag + 8 * H_DIM);
            cp16(&Bs[buf ^ 1][lk][lc],     Bg);
            cp16(&Bs[buf ^ 1][lk + 8][lc], Bg + 8 * J_DIM);
            asm volatile("cp.async.commit_group;");
        }
#pragma unroll
        for (int k = 0; k < BK1; k++) {
            ulonglong2 A0 = *(const ulonglong2*)&As[buf][k][ty << 2];
            ulonglong2 A1 = *(const ulonglong2*)&As[buf][k][(ty << 2) + 64];
            float4 rb0 = *(const float4*)&Bs[buf][k][tx << 2];
            float4 rb1 = *(const float4*)&Bs[buf][k][(tx << 2) + 64];
            unsigned long long ap[4] = {A0.x, A0.y, A1.x, A1.y};
            float rb[8] = {rb0.x, rb0.y, rb0.z, rb0.w, rb1.x, rb1.y, rb1.z, rb1.w};
#pragma unroll
            for (int j = 0; j < 8; j++) {
                unsigned long long bb = bcast2(rb[j]);
#pragma unroll
                for (int p = 0; p < 4; p++)
                    fma2(acc[p][j], ap[p], bb);
            }
        }
        if (s < 512 / BK1) {
            asm volatile("cp.async.wait_group 0;");
            __syncthreads();
            buf ^= 1;
        }
    }

#pragma unroll
    for (int p = 0; p < 4; p++) {
        int mLo = m0 + (ty << 2) + ((p < 2) ? (p << 1) : (64 + ((p - 2) << 1)));
        float lo[8], hi[8];
#pragma unroll
        for (int j = 0; j < 8; j++) unpack2(acc[p][j], lo[j], hi[j]);
        float* r0 = Ct + mLo * J_DIM + n0 + (tx << 2);
        float* r1 = r0 + J_DIM;
        *(float4*)r0        = make_float4(lo[0], lo[1], lo[2], lo[3]);
        *(float4*)(r0 + 64) = make_float4(lo[4], lo[5], lo[6], lo[7]);
        *(float4*)r1        = make_float4(hi[0], hi[1], hi[2], hi[3]);
        *(float4*)(r1 + 64) = make_float4(hi[4], hi[5], hi[6], hi[7]);
    }
}

// ---------------------------------------------------------------------------
// BN stats: one CTA per channel, fp64 accumulate, 2 float4 streams (MLP=2).
// ---------------------------------------------------------------------------
__global__ __launch_bounds__(256) void bn_stats(
    const float* __restrict__ X, int tStride,
    float* __restrict__ meanOut, float* __restrict__ rstdOut) {
    int ch = blockIdx.x;
    const float* base = X + ch * J_DIM;
    double s1a = 0.0, s2a = 0.0, s1b = 0.0, s2b = 0.0;
    for (int t = 0; t < T_DIM; t++) {
        const float* p = base + t * tStride;
        for (int j = threadIdx.x * 8; j + 7 < J_DIM; j += 2048) {
            float4 va = *(const float4*)&p[j];
            float4 vb = *(const float4*)&p[j + 4];
            double a0 = va.x, a1 = va.y, a2 = va.z, a3 = va.w;
            double b0 = vb.x, b1 = vb.y, b2 = vb.z, b3 = vb.w;
            s1a += a0 + a1 + a2 + a3;
            s2a += a0 * a0 + a1 * a1 + a2 * a2 + a3 * a3;
            s1b += b0 + b1 + b2 + b3;
            s2b += b0 * b0 + b1 * b1 + b2 * b2 + b3 * b3;
        }
    }
    __shared__ double sh1[256];
    __shared__ double sh2[256];
    sh1[threadIdx.x] = s1a + s1b;
    sh2[threadIdx.x] = s2a + s2b;
    __syncthreads();
    for (int s = 128; s > 0; s >>= 1) {
        if (threadIdx.x < s) {
            sh1[threadIdx.x] += sh1[threadIdx.x + s];
            sh2[threadIdx.x] += sh2[threadIdx.x + s];
        }
        __syncthreads();
    }
    if (threadIdx.x == 0) {
        double n    = (double)T_DIM * (double)J_DIM;
        double mean = sh1[0] / n;
        double var  = sh2[0] / n - mean * mean;
        meanOut[ch] = (float)mean;
        rstdOut[ch] = __frsqrt_rn(__fadd_rn((float)var, 1e-5f));
    }
}

// ---------------------------------------------------------------------------
// BN1 + LIF1 -> spike bitmask only.
// ---------------------------------------------------------------------------
__global__ __launch_bounds__(256) void lif1_mask(
    const float* __restrict__ gamma, const float* __restrict__ beta) {
    int gw   = (blockIdx.x << 3) + (threadIdx.x >> 5);  // global warp id
    int lane = threadIdx.x & 31;
    int h  = gw & (H_DIM - 1);
    int jw = gw >> 11;                                   // 0..195
    float m = g_mean1[h], r = g_rstd1[h];
    float g = gamma[h],   bt = beta[h];
    const float* p = g_h + h * J_DIM + (jw << 5) + lane;
    float v = 0.0f;
#pragma unroll
    for (int t = 0; t < T_DIM; t++) {
        float x = p[t * HJ];
        x = __fadd_rn(__fmul_rn(__fmul_rn(__fsub_rn(x, m), r), g), bt);
        v = __fadd_rn(v, __fmul_rn(__fsub_rn(x, v), 0.5f));
        unsigned mw = __ballot_sync(0xffffffffu, v >= 1.0f);
        if (lane == 0) g_mask[(t * JW + jw) * H_DIM + h] = mw;
        v = (v >= 1.0f) ? 0.0f : v;
    }
}

// ---------------------------------------------------------------------------
// K4: sparse spike GEMM, 2 columns per warp (R11/R13 scalar version —
// best measured; converged).
// ---------------------------------------------------------------------------
__global__ __launch_bounds__(1024) void spmm2() {
    __shared__ __align__(16) unsigned char shraw[128 * 65 * 4];  // 33.3 KB
    unsigned* words0 = (unsigned*)shraw;                // [2048] masks for jw0
    unsigned* words1 = (unsigned*)shraw + H_DIM;        // [2048] masks for jw0+1
    float*    buf    = (float*)shraw;                   // epilogue: 128 x 65

    int tid  = threadIdx.x;
    int w    = tid >> 5;                     // warp id = local column (0..31)
    int lane = tid & 31;
    int j0   = blockIdx.x * 64;
    int jw0  = blockIdx.x * 2;
    int t    = blockIdx.y;

    // Phase 1: contiguous mask loads for both jw blocks.
    {
        const unsigned* mp0 = g_mask + (t * JW + jw0)     * H_DIM;
        const unsigned* mp1 = g_mask + (t * JW + jw0 + 1) * H_DIM;
        words0[tid]        = mp0[tid];
        words0[tid + 1024] = mp0[tid + 1024];
        words1[tid]        = mp1[tid];
        words1[tid + 1024] = mp1[tid + 1024];
    }
    __syncthreads();

    // Phase 2: gather active rows for columns A = j0+w, B = j0+32+w.
    float4 aA0 = make_float4(0.f, 0.f, 0.f, 0.f);
    float4 aA1 = aA0, aA2 = aA0, aA3 = aA0;
    float4 aB0 = aA0, aB1 = aA0, aB2 = aA0, aB3 = aA0;
    int c0 = lane << 2;
    for (int wi = 0; wi < H_DIM / 32; wi++) {
        unsigned bA = (words0[(wi << 5) + lane] >> w) & 1u;
        unsigned bB = (words1[(wi << 5) + lane] >> w) & 1u;
        unsigned mA = __ballot_sync(0xffffffffu, bA);
        unsigned mB = __ballot_sync(0xffffffffu, bB);
        unsigned mU = mA | mB;
        while (mU) {
            int b = __ffs(mU) - 1;
            mU &= mU - 1;
            int h = (wi << 5) + b;
            const float* rp = g_w2T + h * C_DIM + c0;
            float4 v0 = *(const float4*)(rp);
            float4 v1 = *(const float4*)(rp + 128);
            float4 v2 = *(const float4*)(rp + 256);
            float4 v3 = *(const float4*)(rp + 384);
            if ((mA >> b) & 1u) {
                aA0.x += v0.x; aA0.y += v0.y; aA0.z += v0.z; aA0.w += v0.w;
                aA1.x += v1.x; aA1.y += v1.y; aA1.z += v1.z; aA1.w += v1.w;
                aA2.x += v2.x; aA2.y += v2.y; aA2.z += v2.z; aA2.w += v2.w;
                aA3.x += v3.x; aA3.y += v3.y; aA3.z += v3.z; aA3.w += v3.w;
            }
            if ((mB >> b) & 1u) {
                aB0.x += v0.x; aB0.y += v0.y; aB0.z += v0.z; aB0.w += v0.w;
                aB1.x += v1.x; aB1.y += v1.y; aB1.z += v1.z; aB1.w += v1.w;
                aB2.x += v2.x; aB2.y += v2.y; aB2.z += v2.z; aB2.w += v2.w;
                aB3.x += v3.x; aB3.y += v3.y; aB3.z += v3.z; aB3.w += v3.w;
            }
        }
    }

    // Epilogue: per q, stage 128 c-rows x 64 cols (stride 65), write coalesced.
#pragma unroll
    for (int q = 0; q < 4; q++) {
        float4 vA = (q == 0) ? aA0 : (q == 1) ? aA1 : (q == 2) ? aA2 : aA3;
        float4 vB = (q == 0) ? aB0 : (q == 1) ? aB1 : (q == 2) ? aB2 : aB3;
        __syncthreads();                     // protects mask region reuse / buf reuse
        float fa[4] = {vA.x, vA.y, vA.z, vA.w};
        float fb[4] = {vB.x, vB.y, vB.z, vB.w};
#pragma unroll
        for (int i = 0; i < 4; i++) {
            buf[(c0 + i) * 65 + w]      = fa[i];
            buf[(c0 + i) * 65 + 32 + w] = fb[i];
        }
        __syncthreads();
#pragma unroll
        for (int e0 = 0; e0 < 2; e0++) {
            int e  = tid + e0 * 1024;        // 2048 float4 = 128 rows x 16
            int cl = e >> 4;
            int jj = (e & 15) << 2;
            float4 o;
            o.x = buf[cl * 65 + jj + 0];
            o.y = buf[cl * 65 + jj + 1];
            o.z = buf[cl * 65 + jj + 2];
            o.w = buf[cl * 65 + jj + 3];
            *(float4*)&g_o[t * CJ + (q * 128 + cl) * J_DIM + j0 + jj] = o;
        }
    }
}

// ---------------------------------------------------------------------------
// BN2 + LIF2 + transpose to (T,B,C,N), float4.
// ---------------------------------------------------------------------------
__global__ __launch_bounds__(256) void bn_lif2(
    const float* __restrict__ gamma, const float* __restrict__ beta,
    float* __restrict__ out) {
    int idx = blockIdx.x * blockDim.x + threadIdx.x;   // over CJ/4
    int base = idx << 2;
    int c = base / J_DIM;
    int j = base - c * J_DIM;
    int b = j / N_DIM;
    int n = j - b * N_DIM;
    float m = g_mean2[c], r = g_rstd2[c];
    float g = gamma[c],   bt = beta[c];
    float v0 = 0.f, v1 = 0.f, v2 = 0.f, v3 = 0.f;
#pragma unroll
    for (int t = 0; t < T_DIM; t++) {
        float4 x = *(const float4*)&g_o[base + t * CJ];
        float a0 = __fadd_rn(__fmul_rn(__fmul_rn(__fsub_rn(x.x, m), r), g), bt);
        float a1 = __fadd_rn(__fmul_rn(__fmul_rn(__fsub_rn(x.y, m), r), g), bt);
        float a2 = __fadd_rn(__fmul_rn(__fmul_rn(__fsub_rn(x.z, m), r), g), bt);
        float a3 = __fadd_rn(__fmul_rn(__fmul_rn(__fsub_rn(x.w, m), r), g), bt);
        v0 = __fadd_rn(v0, __fmul_rn(__fsub_rn(a0, v0), 0.5f));
        v1 = __fadd_rn(v1, __fmul_rn(__fsub_rn(a1, v1), 0.5f));
        v2 = __fadd_rn(v2, __fmul_rn(__fsub_rn(a2, v2), 0.5f));
        v3 = __fadd_rn(v3, __fmul_rn(__fsub_rn(a3, v3), 0.5f));
        float4 s;
        s.x = (v0 >= 1.0f) ? 1.0f : 0.0f;
        s.y = (v1 >= 1.0f) ? 1.0f : 0.0f;
        s.z = (v2 >= 1.0f) ? 1.0f : 0.0f;
        s.w = (v3 >= 1.0f) ? 1.0f : 0.0f;
        *(float4*)&out[((t * B_DIM + b) * C_DIM + c) * N_DIM + n] = s;
        v0 = (v0 >= 1.0f) ? 0.0f : v0;
        v1 = (v1 >= 1.0f) ? 0.0f : v1;
        v2 = (v2 >= 1.0f) ? 0.0f : v2;
        v3 = (v3 >= 1.0f) ? 0.0f : v3;
    }
}

// ---------------------------------------------------------------------------
// kernel_launch. Inputs: 0:x 1:w1 2:g1 3:b1 4:w2 5:g2 6:b2
// ---------------------------------------------------------------------------
extern "C" void kernel_launch(void* const* d_in, const int* in_sizes, int n_in,
                              void* d_out, int out_size) {
    const float* x  = (const float*)d_in[0];
    const float* w1 = (const float*)d_in[1];
    const float* g1 = (const float*)d_in[2];
    const float* b1 = (const float*)d_in[3];
    const float* w2 = (const float*)d_in[4];
    const float* g2 = (const float*)d_in[5];
    const float* b2 = (const float*)d_in[6];
    float* out = (float*)d_out;

    float *p_xT, *p_w1T, *p_h, *p_o, *p_m1, *p_r1, *p_m2, *p_r2;
    cudaGetSymbolAddress((void**)&p_xT,  g_xT);
    cudaGetSymbolAddress((void**)&p_w1T, g_w1T);
    cudaGetSymbolAddress((void**)&p_h,   g_h);
    cudaGetSymbolAddress((void**)&p_o,   g_o);
    cudaGetSymbolAddress((void**)&p_m1,  g_mean1);
    cudaGetSymbolAddress((void**)&p_r1,  g_rstd1);
    cudaGetSymbolAddress((void**)&p_m2,  g_mean2);
    cudaGetSymbolAddress((void**)&p_r2,  g_rstd2);

    transpose_x<<<(T_DIM * CJ / 4) / 256, 256>>>(x);                        // 1
    transpose_w<<<dim3(H_DIM / 32, C_DIM / 32, 2), dim3(32, 8)>>>(w1, w2);  // 2
    sgemm1<<<dim3(H_DIM / 128, J_DIM / 128, T_DIM), 256>>>(p_w1T, p_xT, p_h); // 3
    bn_stats<<<H_DIM, 256>>>(p_h, HJ, p_m1, p_r1);                          // 4
    lif1_mask<<<(H_DIM * JW) / 8, 256>>>(g1, b1);                           // 5
    spmm2<<<dim3(J_DIM / 64, T_DIM), 1024>>>();                             // 6
    bn_stats<<<C_DIM, 256>>>(p_o, CJ, p_m2, p_r2);                          // 7
    bn_lif2<<<(CJ / 4) / 256, 256>>>(g2, b2, out);                          // 8
}

// round 17
// speedup vs baseline: 1.0644x; 1.0393x over previous
#include <cuda_runtime.h>

// Problem dims
#define T_DIM 4
#define B_DIM 32
#define C_DIM 512
#define N_DIM 196
#define H_DIM 2048
#define J_DIM (B_DIM * N_DIM)          // 6272 = 49 * 128
#define JW    (J_DIM / 32)             // 196 mask words per (t,h)
#define HJ (H_DIM * J_DIM)             // 12,845,056
#define CJ (C_DIM * J_DIM)             //  3,211,264

// Scratch (static device memory)
__device__ float    g_xT[T_DIM * CJ];       // x transposed: (t, c, j)
__device__ float    g_w1T[C_DIM * H_DIM];   // w1 transposed to [C, H] (k-major)
__device__ float    g_h[T_DIM * HJ];        // hidden pre-act
__device__ float    g_o[T_DIM * CJ];        // output pre-act
__device__ float    g_w2T[H_DIM * C_DIM];   // w2 transposed to [H, C]
__device__ unsigned g_mask[T_DIM * JW * H_DIM]; // spike bits, layout [t][jw][h]
__device__ float    g_mean1[H_DIM];
__device__ float    g_rstd1[H_DIM];
__device__ float    g_mean2[C_DIM];
__device__ float    g_rstd2[C_DIM];

// ---- packed fp32x2 helpers --------------------------------------------------
__device__ __forceinline__ unsigned long long bcast2(float s) {
    unsigned long long d;
    asm("mov.b64 %0, {%1, %1};" : "=l"(d) : "f"(s));
    return d;
}
__device__ __forceinline__ void fma2(unsigned long long& acc,
                                     unsigned long long a,
                                     unsigned long long b) {
    asm("fma.rn.f32x2 %0, %1, %2, %0;" : "+l"(acc) : "l"(a), "l"(b));
}
__device__ __forceinline__ void unpack2(unsigned long long v, float& lo, float& hi) {
    asm("mov.b64 {%0, %1}, %2;" : "=f"(lo), "=f"(hi) : "l"(v));
}
__device__ __forceinline__ void cp16(void* smem_dst, const void* gmem_src) {
    unsigned s = (unsigned)__cvta_generic_to_shared(smem_dst);
    asm volatile("cp.async.cg.shared.global [%0], [%1], 16;" :: "r"(s), "l"(gmem_src));
}

// ---------------------------------------------------------------------------
// K0: transpose x (t,b,c,n) -> g_xT (t,c,j=b*n), float4 both sides.
// ---------------------------------------------------------------------------
__global__ void transpose_x(const float* __restrict__ x) {
    int idx = blockIdx.x * blockDim.x + threadIdx.x;   // over T*CJ/4
    int base = idx << 2;
    int t   = base / CJ;
    int rem = base - t * CJ;
    int c   = rem / J_DIM;
    int j   = rem - c * J_DIM;
    int b   = j / N_DIM;
    int n   = j - b * N_DIM;                            // n%4==0, n+3<196
    float4 v = *(const float4*)&x[((t * B_DIM + b) * C_DIM + c) * N_DIM + n];
    *(float4*)&g_xT[base] = v;
}

// ---------------------------------------------------------------------------
// K0ab: transpose both weights in one launch.
// z=0: w1 [H,C] -> g_w1T [C,H].  z=1: w2 [C,H] -> g_w2T [H,C].
// ---------------------------------------------------------------------------
__global__ void transpose_w(const float* __restrict__ w1,
                            const float* __restrict__ w2) {
    __shared__ float tile[32][33];
    int h0 = blockIdx.x * 32, c0 = blockIdx.y * 32;
    if (blockIdx.z == 0) {
        for (int r = threadIdx.y; r < 32; r += 8)
            tile[r][threadIdx.x] = w1[(h0 + r) * C_DIM + c0 + threadIdx.x];
        __syncthreads();
        for (int r = threadIdx.y; r < 32; r += 8)
            g_w1T[(c0 + r) * H_DIM + h0 + threadIdx.x] = tile[threadIdx.x][r];
    } else {
        for (int r = threadIdx.y; r < 32; r += 8)
            tile[r][threadIdx.x] = w2[(c0 + r) * H_DIM + h0 + threadIdx.x];
        __syncthreads();
        for (int r = threadIdx.y; r < 32; r += 8)
            g_w2T[(h0 + r) * C_DIM + c0 + threadIdx.x] = tile[threadIdx.x][r];
    }
}

// ---------------------------------------------------------------------------
// K1: SGEMM h = w1T^T @ xT per t. FFMA2 inner, 2-stage cp.async pipeline.
// (Converged best: 128x128 tile, BK=16, 256 threads, 8x8/thread.)
// ---------------------------------------------------------------------------
#define BK1 16
__global__ __launch_bounds__(256, 2) void sgemm1(
    const float* __restrict__ A, const float* __restrict__ B,
    float* __restrict__ C) {
    __shared__ float As[2][BK1][128];
    __shared__ float Bs[2][BK1][128];

    const float* Bt = B + blockIdx.z * CJ;
    float*       Ct = C + blockIdx.z * HJ;

    int tid = threadIdx.x;
    int m0 = blockIdx.x * 128;
    int n0 = blockIdx.y * 128;

    int tx = tid & 15;
    int ty = tid >> 4;

    int lk = tid >> 5;
    int lc = (tid & 31) << 2;
    const float* Agp = A  + lk * H_DIM + m0 + lc;
    const float* Bgp = Bt + lk * J_DIM + n0 + lc;

    unsigned long long acc[4][8];
#pragma unroll
    for (int p = 0; p < 4; p++)
#pragma unroll
        for (int j = 0; j < 8; j++) acc[p][j] = 0ull;

    cp16(&As[0][lk][lc],     Agp);
    cp16(&As[0][lk + 8][lc], Agp + 8 * H_DIM);
    cp16(&Bs[0][lk][lc],     Bgp);
    cp16(&Bs[0][lk + 8][lc], Bgp + 8 * J_DIM);
    asm volatile("cp.async.commit_group;");
    asm volatile("cp.async.wait_group 0;");
    __syncthreads();

    int buf = 0;
    for (int s = 1; s <= 512 / BK1; s++) {
        if (s < 512 / BK1) {
            const float* Ag = Agp + s * BK1 * H_DIM;
            const float* Bg = Bgp + s * BK1 * J_DIM;
            cp16(&As[buf ^ 1][lk][lc],     Ag);
            cp16(&As[buf ^ 1][lk + 8][lc], Ag + 8 * H_DIM);
            cp16(&Bs[buf ^ 1][lk][lc],     Bg);
            cp16(&Bs[buf ^ 1][lk + 8][lc], Bg + 8 * J_DIM);
            asm volatile("cp.async.commit_group;");
        }
#pragma unroll
        for (int k = 0; k < BK1; k++) {
            ulonglong2 A0 = *(const ulonglong2*)&As[buf][k][ty << 2];
            ulonglong2 A1 = *(const ulonglong2*)&As[buf][k][(ty << 2) + 64];
            float4 rb0 = *(const float4*)&Bs[buf][k][tx << 2];
            float4 rb1 = *(const float4*)&Bs[buf][k][(tx << 2) + 64];
            unsigned long long ap[4] = {A0.x, A0.y, A1.x, A1.y};
            float rb[8] = {rb0.x, rb0.y, rb0.z, rb0.w, rb1.x, rb1.y, rb1.z, rb1.w};
#pragma unroll
            for (int j = 0; j < 8; j++) {
                unsigned long long bb = bcast2(rb[j]);
#pragma unroll
                for (int p = 0; p < 4; p++)
                    fma2(acc[p][j], ap[p], bb);
            }
        }
        if (s < 512 / BK1) {
            asm volatile("cp.async.wait_group 0;");
            __syncthreads();
            buf ^= 1;
        }
    }

#pragma unroll
    for (int p = 0; p < 4; p++) {
        int mLo = m0 + (ty << 2) + ((p < 2) ? (p << 1) : (64 + ((p - 2) << 1)));
        float lo[8], hi[8];
#pragma unroll
        for (int j = 0; j < 8; j++) unpack2(acc[p][j], lo[j], hi[j]);
        float* r0 = Ct + mLo * J_DIM + n0 + (tx << 2);
        float* r1 = r0 + J_DIM;
        *(float4*)r0        = make_float4(lo[0], lo[1], lo[2], lo[3]);
        *(float4*)(r0 + 64) = make_float4(lo[4], lo[5], lo[6], lo[7]);
        *(float4*)r1        = make_float4(hi[0], hi[1], hi[2], hi[3]);
        *(float4*)(r1 + 64) = make_float4(hi[4], hi[5], hi[6], hi[7]);
    }
}

// ---------------------------------------------------------------------------
// BN stats: one CTA per channel, fp64 accumulate, 2 float4 streams (MLP=2).
// ---------------------------------------------------------------------------
__global__ __launch_bounds__(256) void bn_stats(
    const float* __restrict__ X, int tStride,
    float* __restrict__ meanOut, float* __restrict__ rstdOut) {
    int ch = blockIdx.x;
    const float* base = X + ch * J_DIM;
    double s1a = 0.0, s2a = 0.0, s1b = 0.0, s2b = 0.0;
    for (int t = 0; t < T_DIM; t++) {
        const float* p = base + t * tStride;
        for (int j = threadIdx.x * 8; j + 7 < J_DIM; j += 2048) {
            float4 va = *(const float4*)&p[j];
            float4 vb = *(const float4*)&p[j + 4];
            double a0 = va.x, a1 = va.y, a2 = va.z, a3 = va.w;
            double b0 = vb.x, b1 = vb.y, b2 = vb.z, b3 = vb.w;
            s1a += a0 + a1 + a2 + a3;
            s2a += a0 * a0 + a1 * a1 + a2 * a2 + a3 * a3;
            s1b += b0 + b1 + b2 + b3;
            s2b += b0 * b0 + b1 * b1 + b2 * b2 + b3 * b3;
        }
    }
    __shared__ double sh1[256];
    __shared__ double sh2[256];
    sh1[threadIdx.x] = s1a + s1b;
    sh2[threadIdx.x] = s2a + s2b;
    __syncthreads();
    for (int s = 128; s > 0; s >>= 1) {
        if (threadIdx.x < s) {
            sh1[threadIdx.x] += sh1[threadIdx.x + s];
            sh2[threadIdx.x] += sh2[threadIdx.x + s];
        }
        __syncthreads();
    }
    if (threadIdx.x == 0) {
        double n    = (double)T_DIM * (double)J_DIM;
        double mean = sh1[0] / n;
        double var  = sh2[0] / n - mean * mean;
        meanOut[ch] = (float)mean;
        rstdOut[ch] = __frsqrt_rn(__fadd_rn((float)var, 1e-5f));
    }
}

// ---------------------------------------------------------------------------
// BN1 + LIF1 -> spike bitmask only. All 4 t-loads hoisted (MLP=4); the
// LIF recurrence then runs on registers. Arithmetic order unchanged.
// ---------------------------------------------------------------------------
__global__ __launch_bounds__(256) void lif1_mask(
    const float* __restrict__ gamma, const float* __restrict__ beta) {
    int gw   = (blockIdx.x << 3) + (threadIdx.x >> 5);  // global warp id
    int lane = threadIdx.x & 31;
    int h  = gw & (H_DIM - 1);
    int jw = gw >> 11;                                   // 0..195
    float m = g_mean1[h], r = g_rstd1[h];
    float g = gamma[h],   bt = beta[h];
    const float* p = g_h + h * J_DIM + (jw << 5) + lane;

    float xs[T_DIM];
#pragma unroll
    for (int t = 0; t < T_DIM; t++) xs[t] = p[t * HJ];   // independent loads

    float v = 0.0f;
#pragma unroll
    for (int t = 0; t < T_DIM; t++) {
        float x = __fadd_rn(__fmul_rn(__fmul_rn(__fsub_rn(xs[t], m), r), g), bt);
        v = __fadd_rn(v, __fmul_rn(__fsub_rn(x, v), 0.5f));
        unsigned mw = __ballot_sync(0xffffffffu, v >= 1.0f);
        if (lane == 0) g_mask[(t * JW + jw) * H_DIM + h] = mw;
        v = (v >= 1.0f) ? 0.0f : v;
    }
}

// ---------------------------------------------------------------------------
// K4: sparse spike GEMM, 2 columns per warp (converged best).
// CTA = 64 j-columns x one t (392 CTAs): warp w owns j0+w and j0+32+w.
// ---------------------------------------------------------------------------
__global__ __launch_bounds__(1024) void spmm2() {
    __shared__ __align__(16) unsigned char shraw[128 * 65 * 4];  // 33.3 KB
    unsigned* words0 = (unsigned*)shraw;                // [2048] masks for jw0
    unsigned* words1 = (unsigned*)shraw + H_DIM;        // [2048] masks for jw0+1
    float*    buf    = (float*)shraw;                   // epilogue: 128 x 65

    int tid  = threadIdx.x;
    int w    = tid >> 5;                     // warp id = local column (0..31)
    int lane = tid & 31;
    int j0   = blockIdx.x * 64;
    int jw0  = blockIdx.x * 2;
    int t    = blockIdx.y;

    // Phase 1: contiguous mask loads for both jw blocks.
    {
        const unsigned* mp0 = g_mask + (t * JW + jw0)     * H_DIM;
        const unsigned* mp1 = g_mask + (t * JW + jw0 + 1) * H_DIM;
        words0[tid]        = mp0[tid];
        words0[tid + 1024] = mp0[tid + 1024];
        words1[tid]        = mp1[tid];
        words1[tid + 1024] = mp1[tid + 1024];
    }
    __syncthreads();

    // Phase 2: gather active rows for columns A = j0+w, B = j0+32+w.
    float4 aA0 = make_float4(0.f, 0.f, 0.f, 0.f);
    float4 aA1 = aA0, aA2 = aA0, aA3 = aA0;
    float4 aB0 = aA0, aB1 = aA0, aB2 = aA0, aB3 = aA0;
    int c0 = lane << 2;
    for (int wi = 0; wi < H_DIM / 32; wi++) {
        unsigned bA = (words0[(wi << 5) + lane] >> w) & 1u;
        unsigned bB = (words1[(wi << 5) + lane] >> w) & 1u;
        unsigned mA = __ballot_sync(0xffffffffu, bA);
        unsigned mB = __ballot_sync(0xffffffffu, bB);
        unsigned mU = mA | mB;
        while (mU) {
            int b = __ffs(mU) - 1;
            mU &= mU - 1;
            int h = (wi << 5) + b;
            const float* rp = g_w2T + h * C_DIM + c0;
            float4 v0 = *(const float4*)(rp);
            float4 v1 = *(const float4*)(rp + 128);
            float4 v2 = *(const float4*)(rp + 256);
            float4 v3 = *(const float4*)(rp + 384);
            if ((mA >> b) & 1u) {
                aA0.x += v0.x; aA0.y += v0.y; aA0.z += v0.z; aA0.w += v0.w;
                aA1.x += v1.x; aA1.y += v1.y; aA1.z += v1.z; aA1.w += v1.w;
                aA2.x += v2.x; aA2.y += v2.y; aA2.z += v2.z; aA2.w += v2.w;
                aA3.x += v3.x; aA3.y += v3.y; aA3.z += v3.z; aA3.w += v3.w;
            }
            if ((mB >> b) & 1u) {
                aB0.x += v0.x; aB0.y += v0.y; aB0.z += v0.z; aB0.w += v0.w;
                aB1.x += v1.x; aB1.y += v1.y; aB1.z += v1.z; aB1.w += v1.w;
                aB2.x += v2.x; aB2.y += v2.y; aB2.z += v2.z; aB2.w += v2.w;
                aB3.x += v3.x; aB3.y += v3.y; aB3.z += v3.z; aB3.w += v3.w;
            }
        }
    }

    // Epilogue: per q, stage 128 c-rows x 64 cols (stride 65), write coalesced.
#pragma unroll
    for (int q = 0; q < 4; q++) {
        float4 vA = (q == 0) ? aA0 : (q == 1) ? aA1 : (q == 2) ? aA2 : aA3;
        float4 vB = (q == 0) ? aB0 : (q == 1) ? aB1 : (q == 2) ? aB2 : aB3;
        __syncthreads();                     // protects mask region reuse / buf reuse
        float fa[4] = {vA.x, vA.y, vA.z, vA.w};
        float fb[4] = {vB.x, vB.y, vB.z, vB.w};
#pragma unroll
        for (int i = 0; i < 4; i++) {
            buf[(c0 + i) * 65 + w]      = fa[i];
            buf[(c0 + i) * 65 + 32 + w] = fb[i];
        }
        __syncthreads();
#pragma unroll
        for (int e0 = 0; e0 < 2; e0++) {
            int e  = tid + e0 * 1024;        // 2048 float4 = 128 rows x 16
            int cl = e >> 4;
            int jj = (e & 15) << 2;
            float4 o;
            o.x = buf[cl * 65 + jj + 0];
            o.y = buf[cl * 65 + jj + 1];
            o.z = buf[cl * 65 + jj + 2];
            o.w = buf[cl * 65 + jj + 3];
            *(float4*)&g_o[t * CJ + (q * 128 + cl) * J_DIM + j0 + jj] = o;
        }
    }
}

// ---------------------------------------------------------------------------
// BN2 + LIF2 + transpose to (T,B,C,N). All 4 t-loads hoisted (MLP=4).
// Arithmetic order per element unchanged.
// ---------------------------------------------------------------------------
__global__ __launch_bounds__(256) void bn_lif2(
    const float* __restrict__ gamma, const float* __restrict__ beta,
    float* __restrict__ out) {
    int idx = blockIdx.x * blockDim.x + threadIdx.x;   // over CJ/4
    int base = idx << 2;
    int c = base / J_DIM;
    int j = base - c * J_DIM;
    int b = j / N_DIM;
    int n = j - b * N_DIM;
    float m = g_mean2[c], r = g_rstd2[c];
    float g = gamma[c],   bt = beta[c];

    float4 xs[T_DIM];
#pragma unroll
    for (int t = 0; t < T_DIM; t++) xs[t] = *(const float4*)&g_o[base + t * CJ];

    float v0 = 0.f, v1 = 0.f, v2 = 0.f, v3 = 0.f;
#pragma unroll
    for (int t = 0; t < T_DIM; t++) {
        float4 x = xs[t];
        float a0 = __fadd_rn(__fmul_rn(__fmul_rn(__fsub_rn(x.x, m), r), g), bt);
        float a1 = __fadd_rn(__fmul_rn(__fmul_rn(__fsub_rn(x.y, m), r), g), bt);
        float a2 = __fadd_rn(__fmul_rn(__fmul_rn(__fsub_rn(x.z, m), r), g), bt);
        float a3 = __fadd_rn(__fmul_rn(__fmul_rn(__fsub_rn(x.w, m), r), g), bt);
        v0 = __fadd_rn(v0, __fmul_rn(__fsub_rn(a0, v0), 0.5f));
        v1 = __fadd_rn(v1, __fmul_rn(__fsub_rn(a1, v1), 0.5f));
        v2 = __fadd_rn(v2, __fmul_rn(__fsub_rn(a2, v2), 0.5f));
        v3 = __fadd_rn(v3, __fmul_rn(__fsub_rn(a3, v3), 0.5f));
        float4 s;
        s.x = (v0 >= 1.0f) ? 1.0f : 0.0f;
        s.y = (v1 >= 1.0f) ? 1.0f : 0.0f;
        s.z = (v2 >= 1.0f) ? 1.0f : 0.0f;
        s.w = (v3 >= 1.0f) ? 1.0f : 0.0f;
        *(float4*)&out[((t * B_DIM + b) * C_DIM + c) * N_DIM + n] = s;
        v0 = (v0 >= 1.0f) ? 0.0f : v0;
        v1 = (v1 >= 1.0f) ? 0.0f : v1;
        v2 = (v2 >= 1.0f) ? 0.0f : v2;
        v3 = (v3 >= 1.0f) ? 0.0f : v3;
    }
}

// ---------------------------------------------------------------------------
// kernel_launch. Inputs: 0:x 1:w1 2:g1 3:b1 4:w2 5:g2 6:b2
// ---------------------------------------------------------------------------
extern "C" void kernel_launch(void* const* d_in, const int* in_sizes, int n_in,
                              void* d_out, int out_size) {
    const float* x  = (const float*)d_in[0];
    const float* w1 = (const float*)d_in[1];
    const float* g1 = (const float*)d_in[2];
    const float* b1 = (const float*)d_in[3];
    const float* w2 = (const float*)d_in[4];
    const float* g2 = (const float*)d_in[5];
    const float* b2 = (const float*)d_in[6];
    float* out = (float*)d_out;

    float *p_xT, *p_w1T, *p_h, *p_o, *p_m1, *p_r1, *p_m2, *p_r2;
    cudaGetSymbolAddress((void**)&p_xT,  g_xT);
    cudaGetSymbolAddress((void**)&p_w1T, g_w1T);
    cudaGetSymbolAddress((void**)&p_h,   g_h);
    cudaGetSymbolAddress((void**)&p_o,   g_o);
    cudaGetSymbolAddress((void**)&p_m1,  g_mean1);
    cudaGetSymbolAddress((void**)&p_r1,  g_rstd1);
    cudaGetSymbolAddress((void**)&p_m2,  g_mean2);
    cudaGetSymbolAddress((void**)&p_r2,  g_rstd2);

    transpose_x<<<(T_DIM * CJ / 4) / 256, 256>>>(x);                        // 1
    transpose_w<<<dim3(H_DIM / 32, C_DIM / 32, 2), dim3(32, 8)>>>(w1, w2);  // 2
    sgemm1<<<dim3(H_DIM / 128, J_DIM / 128, T_DIM), 256>>>(p_w1T, p_xT, p_h); // 3
    bn_stats<<<H_DIM, 256>>>(p_h, HJ, p_m1, p_r1);                          // 4
    lif1_mask<<<(H_DIM * JW) / 8, 256>>>(g1, b1);                           // 5
    spmm2<<<dim3(J_DIM / 64, T_DIM), 1024>>>();                             // 6
    bn_stats<<<C_DIM, 256>>>(p_o, CJ, p_m2, p_r2);                          // 7
    bn_lif2<<<(CJ / 4) / 256, 256>>>(g2, b2, out);                          // 8
}